// round 2
// baseline (speedup 1.0000x reference)
#include <cuda_runtime.h>
#include <math.h>

// ---------------- scratch (device globals: allocation-free) ----------------
static __device__ float g_wr[1104 * 70];                     // renormed embed
static __device__ float g_e[(size_t)65536 * 70];             // e = x @ wr
static __device__ float g_xg[(size_t)4 * 65536 * 70];        // xg, 4 gate planes [g][m][70]
static __device__ float g_hs[(size_t)65536 * 70];            // lstm hidden states
static __device__ float g_energy[65536];                     // attention energies

#define DEV_INLINE __device__ __forceinline__

// packed fp32x2 FMA (sm_100+): 2 MACs per issue vs 1 for plain FFMA
DEV_INLINE float2 ffma2(float2 a, float2 b, float2 c) {
    unsigned long long ua = *reinterpret_cast<unsigned long long*>(&a);
    unsigned long long ub = *reinterpret_cast<unsigned long long*>(&b);
    unsigned long long uc = *reinterpret_cast<unsigned long long*>(&c);
    unsigned long long ud;
    asm("fma.rn.f32x2 %0, %1, %2, %3;" : "=l"(ud) : "l"(ua), "l"(ub), "l"(uc));
    return *reinterpret_cast<float2*>(&ud);
}

DEV_INLINE float rcp_(float x) { float r; asm("rcp.approx.f32 %0, %1;" : "=f"(r) : "f"(x)); return r; }

// ---------------- K0: renorm embed rows (max_norm=1) ----------------
__global__ void k_renorm(const float* __restrict__ ew) {
    int row = blockIdx.x * 8 + (threadIdx.x >> 5);   // 138*8 = 1104
    int lane = threadIdx.x & 31;
    const float* src = ew + row * 70;
    float s = 0.f;
    for (int k = lane; k < 70; k += 32) { float v = src[k]; s += v * v; }
    #pragma unroll
    for (int o = 16; o > 0; o >>= 1) s += __shfl_xor_sync(0xffffffffu, s, o);
    float n = sqrtf(s);
    float sc = (n > 1.0f) ? 1.0f / (n + 1e-7f) : 1.0f;
    float* dst = g_wr + row * 70;
    for (int k = lane; k < 70; k += 32) dst[k] = src[k] * sc;
}

// ---------------- K1: e = x(65536x1104) @ wr(1104x70), f32x2 inner ----------------
// (unchanged from round 1 — attribution: profile it next round)
__global__ __launch_bounds__(192) void k_egemm(const float* __restrict__ x) {
    __shared__ float  sa[16][132];
    __shared__ float2 sb[16][72];
    const int tid = threadIdx.x;
    const int mb = blockIdx.x * 128;
    const int mg = tid / 12, ng = tid % 12;
    const int m0 = mg * 8, n0 = ng * 6;

    float2 acc[4][6];
    #pragma unroll
    for (int p = 0; p < 4; p++)
        #pragma unroll
        for (int j = 0; j < 6; j++) acc[p][j] = make_float2(0.f, 0.f);

    for (int kt = 0; kt < 1104; kt += 16) {
        for (int i = tid; i < 512; i += 192) {
            int m = i >> 2; int kv = (i & 3) << 2;
            float4 v = *reinterpret_cast<const float4*>(x + (size_t)(mb + m) * 1104 + kt + kv);
            sa[kv + 0][m] = v.x; sa[kv + 1][m] = v.y;
            sa[kv + 2][m] = v.z; sa[kv + 3][m] = v.w;
        }
        for (int i = tid; i < 16 * 72; i += 192) {
            int k = i / 72, n = i % 72;
            float v = (n < 70) ? g_wr[(kt + k) * 70 + n] : 0.f;
            sb[k][n] = make_float2(v, v);
        }
        __syncthreads();
        #pragma unroll
        for (int kk = 0; kk < 16; kk++) {
            float4 a0 = *reinterpret_cast<const float4*>(&sa[kk][m0]);
            float4 a1 = *reinterpret_cast<const float4*>(&sa[kk][m0 + 4]);
            float2 ap[4] = { make_float2(a0.x, a0.y), make_float2(a0.z, a0.w),
                             make_float2(a1.x, a1.y), make_float2(a1.z, a1.w) };
            __align__(16) float2 bv[6];
            *reinterpret_cast<float4*>(&bv[0]) = *reinterpret_cast<const float4*>(&sb[kk][n0]);
            *reinterpret_cast<float4*>(&bv[2]) = *reinterpret_cast<const float4*>(&sb[kk][n0 + 2]);
            *reinterpret_cast<float4*>(&bv[4]) = *reinterpret_cast<const float4*>(&sb[kk][n0 + 4]);
            #pragma unroll
            for (int p = 0; p < 4; p++)
                #pragma unroll
                for (int j = 0; j < 6; j++)
                    acc[p][j] = ffma2(ap[p], bv[j], acc[p][j]);
        }
        __syncthreads();
    }
    #pragma unroll
    for (int p = 0; p < 4; p++) {
        int m = mb + m0 + 2 * p;
        #pragma unroll
        for (int j = 0; j < 6; j++) {
            int n = n0 + j;
            if (n < 70) {
                g_e[(size_t)m * 70 + n]       = acc[p][j].x;
                g_e[(size_t)(m + 1) * 70 + n] = acc[p][j].y;
            }
        }
    }
}

// ---------------- K2: xg plane gi = e(65536x70) @ w_ih[gi]^T + bias, K-paired f32x2 ----------------
// BM=64, BN=70 (one gate plane per blockIdx.y), 160 threads, thread tile 4m x 7u
__global__ __launch_bounds__(160) void k_xggemm(const float* __restrict__ wih,
                                                const float* __restrict__ bih,
                                                const float* __restrict__ bhh) {
    __shared__ float se[64 * 72];     // e rows, stride 72
    __shared__ float sw[70 * 74];     // w rows (this gate), stride 74
    const int tid = threadIdx.x;
    const int mb = blockIdx.x * 64;
    const int gi = blockIdx.y;
    const int mg = tid / 10, jg = tid % 10;
    const int m0 = mg * 4, u0 = jg * 7;

    for (int i = tid; i < 64 * 70; i += 160) {
        int m = i / 70, k = i % 70;
        se[m * 72 + k] = g_e[(size_t)(mb + m) * 70 + k];
    }
    for (int i = tid; i < 70 * 70; i += 160) {
        int u = i / 70, k = i % 70;
        sw[u * 74 + k] = wih[(gi * 70 + u) * 70 + k];
    }
    float2 acc[4][7];
    #pragma unroll
    for (int a = 0; a < 4; a++)
        #pragma unroll
        for (int c = 0; c < 7; c++) acc[a][c] = make_float2(0.f, 0.f);
    __syncthreads();

    #pragma unroll 5
    for (int kp = 0; kp < 35; kp++) {
        float2 av[4], wv[7];
        #pragma unroll
        for (int a = 0; a < 4; a++)
            av[a] = *reinterpret_cast<const float2*>(&se[(m0 + a) * 72 + 2 * kp]);
        #pragma unroll
        for (int c = 0; c < 7; c++)
            wv[c] = *reinterpret_cast<const float2*>(&sw[(u0 + c) * 74 + 2 * kp]);
        #pragma unroll
        for (int a = 0; a < 4; a++)
            #pragma unroll
            for (int c = 0; c < 7; c++)
                acc[a][c] = ffma2(av[a], wv[c], acc[a][c]);
    }
    float bs[7];
    #pragma unroll
    for (int c = 0; c < 7; c++) bs[c] = bih[gi * 70 + u0 + c] + bhh[gi * 70 + u0 + c];
    float* plane = g_xg + (size_t)gi * 65536 * 70;
    #pragma unroll
    for (int a = 0; a < 4; a++)
        #pragma unroll
        for (int c = 0; c < 7; c++)
            plane[(size_t)(mb + m0 + a) * 70 + u0 + c] = acc[a][c].x + acc[a][c].y + bs[c];
}

// ---------------- K3: LSTM recurrence ----------------
// 576 threads: tid = 8u + 2g + p.  Unit u (0..69), gate g (i,f,g,o), K-half p.
// Dot = 9 LDS.128 + 18 ffma2, halves combined via shfl, gates combined via shfl.
// Double-buffered h -> ONE barrier per step.
__global__ __launch_bounds__(576) void k_lstm(const float* __restrict__ whh) {
    __shared__ float s_h[2][72];
    const int b = blockIdx.x, tid = threadIdx.x;
    const int u = tid >> 3, g = (tid >> 1) & 3, p = tid & 1;
    const bool active = (u < 70);

    float2 w[18];
    #pragma unroll
    for (int i = 0; i < 18; i++) w[i] = make_float2(0.f, 0.f);
    if (active) {
        const float* wr = whh + (g * 70 + u) * 70;
        if (p == 0) {
            #pragma unroll
            for (int i = 0; i < 18; i++) w[i] = *reinterpret_cast<const float2*>(wr + 2 * i);
        } else {
            #pragma unroll
            for (int i = 0; i < 17; i++) w[i] = *reinterpret_cast<const float2*>(wr + 36 + 2 * i);
        }
    }
    if (tid < 144) s_h[tid / 72][tid % 72] = 0.f;   // zero both buffers incl. padding

    const float* xp = g_xg + ((size_t)g * 65536 + (size_t)b * 512) * 70 + u;
    float xcur = (active && p == 0) ? xp[0] : 0.f;
    float* hs_out = g_hs + (size_t)b * 512 * 70 + u;
    float c = 0.f;
    __syncthreads();

    int buf = 0;
    for (int t = 0; t < 512; t++) {
        const float4* h4 = reinterpret_cast<const float4*>(&s_h[buf][36 * p]);
        float2 a0 = make_float2(0.f, 0.f), a1 = make_float2(0.f, 0.f);
        #pragma unroll
        for (int i = 0; i < 9; i++) {
            float4 hq = h4[i];
            a0 = ffma2(w[2 * i],     make_float2(hq.x, hq.y), a0);
            a1 = ffma2(w[2 * i + 1], make_float2(hq.z, hq.w), a1);
        }
        float s = (a0.x + a0.y) + (a1.x + a1.y);
        s += __shfl_xor_sync(0xffffffffu, s, 1);

        float xnext = 0.f;
        if (active && p == 0 && t < 511) xnext = xp[(size_t)(t + 1) * 70];

        float act = 0.f;
        if (p == 0) {
            float pre = xcur + s;
            float xs = (g == 2) ? pre + pre : pre;
            float sg = rcp_(1.0f + __expf(-xs));
            act = (g == 2) ? (sg + sg - 1.0f) : sg;    // tanh(x) = 2*sigmoid(2x)-1
        }
        const int L = (tid & 31) & ~7;
        float gi_ = __shfl_sync(0xffffffffu, act, L + 0);
        float gf  = __shfl_sync(0xffffffffu, act, L + 2);
        float gg  = __shfl_sync(0xffffffffu, act, L + 4);
        float go  = __shfl_sync(0xffffffffu, act, L + 6);

        const int nb = buf ^ 1;
        if (((tid & 7) == 0) && active) {
            c = gf * c + gi_ * gg;
            float sg2 = rcp_(1.0f + __expf(-2.0f * c));
            float h = go * (sg2 + sg2 - 1.0f);
            s_h[nb][u] = h;
            hs_out[(size_t)t * 70] = h;
        }
        __syncthreads();
        buf = nb; xcur = xnext;
    }
}

// ---------------- K4: attention energies, fused GEMM + relu + matvec ----------------
// BM=64 rows, 256 threads: mg=tid/8 (2 rows), jg=tid&7 (8 j's, j = jg + 8c)
__global__ __launch_bounds__(256) void k_energy(const float* __restrict__ w1,
                                                const float* __restrict__ b1,
                                                const float* __restrict__ w2,
                                                const float* __restrict__ b2) {
    __shared__ float sh[64 * 72];     // hs rows, stride 72
    __shared__ float sw1[64 * 74];    // w1 rows, stride 74
    const int tid = threadIdx.x;
    const int mb = blockIdx.x * 64;
    const int mg = tid >> 3, jg = tid & 7;

    for (int i = tid; i < 64 * 70; i += 256) {
        int m = i / 70, k = i % 70;
        sh[m * 72 + k] = g_hs[(size_t)(mb + m) * 70 + k];
    }
    for (int i = tid; i < 64 * 70; i += 256) {
        int j = i / 70, k = i % 70;
        sw1[j * 74 + k] = w1[i];
    }
    float2 acc0[8], acc1[8];
    #pragma unroll
    for (int cc = 0; cc < 8; cc++) { acc0[cc] = make_float2(0.f, 0.f); acc1[cc] = make_float2(0.f, 0.f); }
    __syncthreads();

    const int m0 = 2 * mg;
    #pragma unroll 5
    for (int kp = 0; kp < 35; kp++) {
        float2 h0 = *reinterpret_cast<const float2*>(&sh[m0 * 72 + 2 * kp]);
        float2 h1 = *reinterpret_cast<const float2*>(&sh[(m0 + 1) * 72 + 2 * kp]);
        #pragma unroll
        for (int cc = 0; cc < 8; cc++) {
            float2 wv = *reinterpret_cast<const float2*>(&sw1[(jg + 8 * cc) * 74 + 2 * kp]);
            acc0[cc] = ffma2(h0, wv, acc0[cc]);
            acc1[cc] = ffma2(h1, wv, acc1[cc]);
        }
    }
    float r0 = 0.f, r1 = 0.f;
    #pragma unroll
    for (int cc = 0; cc < 8; cc++) {
        int j = jg + 8 * cc;
        float bj = __ldg(&b1[j]), wj = __ldg(&w2[j]);
        float e0 = fmaxf(acc0[cc].x + acc0[cc].y + bj, 0.f);
        float e1 = fmaxf(acc1[cc].x + acc1[cc].y + bj, 0.f);
        r0 += e0 * wj; r1 += e1 * wj;
    }
    #pragma unroll
    for (int o = 4; o > 0; o >>= 1) {
        r0 += __shfl_down_sync(0xffffffffu, r0, o);
        r1 += __shfl_down_sync(0xffffffffu, r1, o);
    }
    if (jg == 0) {
        float bb = __ldg(&b2[0]);
        g_energy[mb + m0]     = r0 + bb;
        g_energy[mb + m0 + 1] = r1 + bb;
    }
}

// ---------------- K5: softmax over S, pooled, fc, final softmax ----------------
__global__ __launch_bounds__(280) void k_finish(const float* __restrict__ fcw,
                                                const float* __restrict__ fcb,
                                                float* __restrict__ out) {
    __shared__ float se[512];
    __shared__ float sr[512];
    __shared__ float s_pool[4][70];
    __shared__ float s_pl[70];
    __shared__ float s_lg[3];
    const int tid = threadIdx.x;
    const int b = blockIdx.x;

    for (int i = tid; i < 512; i += 280) { float v = g_energy[b * 512 + i]; se[i] = v; sr[i] = v; }
    __syncthreads();
    for (int st = 256; st > 0; st >>= 1) {
        for (int i = tid; i < st; i += 280) sr[i] = fmaxf(sr[i], sr[i + st]);
        __syncthreads();
    }
    float mx = sr[0];
    __syncthreads();
    for (int i = tid; i < 512; i += 280) { float ev = __expf(se[i] - mx); se[i] = ev; sr[i] = ev; }
    __syncthreads();
    for (int st = 256; st > 0; st >>= 1) {
        for (int i = tid; i < st; i += 280) sr[i] += sr[i + st];
        __syncthreads();
    }
    float inv = 1.0f / sr[0];

    const int h = tid % 70, ch = tid / 70;
    float p = 0.f;
    const float* base = g_hs + (size_t)b * 512 * 70;
    for (int s = ch; s < 512; s += 4) p += base[(size_t)s * 70 + h] * se[s];
    s_pool[ch][h] = p;
    __syncthreads();
    if (ch == 0) s_pl[h] = (s_pool[0][h] + s_pool[1][h] + s_pool[2][h] + s_pool[3][h]) * inv;
    __syncthreads();
    if (tid < 3) {
        float lg = fcb[tid];
        for (int k = 0; k < 70; k++) lg += s_pl[k] * fcw[tid * 70 + k];
        s_lg[tid] = lg;
    }
    __syncthreads();
    if (tid < 3) {
        float m = fmaxf(s_lg[0], fmaxf(s_lg[1], s_lg[2]));
        float e0 = __expf(s_lg[0] - m), e1 = __expf(s_lg[1] - m), e2 = __expf(s_lg[2] - m);
        float ev = (tid == 0) ? e0 : ((tid == 1) ? e1 : e2);
        out[b * 3 + tid] = ev / (e0 + e1 + e2);
    }
}

// ---------------- launch ----------------
extern "C" void kernel_launch(void* const* d_in, const int* in_sizes, int n_in,
                              void* d_out, int out_size) {
    const float* x   = (const float*)d_in[0];
    const float* ew  = (const float*)d_in[1];
    const float* wih = (const float*)d_in[2];
    const float* whh = (const float*)d_in[3];
    const float* bih = (const float*)d_in[4];
    const float* bhh = (const float*)d_in[5];
    const float* aw1 = (const float*)d_in[6];
    const float* ab1 = (const float*)d_in[7];
    const float* aw2 = (const float*)d_in[8];
    const float* ab2 = (const float*)d_in[9];
    const float* fcw = (const float*)d_in[10];
    const float* fcb = (const float*)d_in[11];
    float* out = (float*)d_out;

    k_renorm<<<138, 256>>>(ew);
    k_egemm<<<512, 192>>>(x);
    k_xggemm<<<dim3(1024, 4), 160>>>(wih, bih, bhh);
    k_lstm<<<128, 576>>>(whh);
    k_energy<<<1024, 256>>>(aw1, ab1, aw2, ab2);
    k_finish<<<128, 280>>>(fcw, fcb, out);
}

// round 3
// speedup vs baseline: 1.6921x; 1.6921x over previous
#include <cuda_runtime.h>
#include <math.h>

// ---------------- scratch (device globals: allocation-free) ----------------
static __device__ float g_wr[1104 * 70];                     // renormed embed
static __device__ float g_e[(size_t)65536 * 70];             // e = x @ wr
static __device__ float g_xg[(size_t)4 * 65536 * 70];        // xg, 4 gate planes [g][m][70]
static __device__ float g_hs[(size_t)65536 * 70];            // lstm hidden states
static __device__ float g_energy[65536];                     // attention energies

#define DEV_INLINE __device__ __forceinline__

// packed fp32x2 FMA (sm_100+): 2 MACs per issue vs 1 for plain FFMA
DEV_INLINE float2 ffma2(float2 a, float2 b, float2 c) {
    unsigned long long ua = *reinterpret_cast<unsigned long long*>(&a);
    unsigned long long ub = *reinterpret_cast<unsigned long long*>(&b);
    unsigned long long uc = *reinterpret_cast<unsigned long long*>(&c);
    unsigned long long ud;
    asm("fma.rn.f32x2 %0, %1, %2, %3;" : "=l"(ud) : "l"(ua), "l"(ub), "l"(uc));
    return *reinterpret_cast<float2*>(&ud);
}

DEV_INLINE float rcp_(float x) { float r; asm("rcp.approx.f32 %0, %1;" : "=f"(r) : "f"(x)); return r; }

// ---------------- K0: renorm embed rows (max_norm=1) ----------------
__global__ void k_renorm(const float* __restrict__ ew) {
    int row = blockIdx.x * 8 + (threadIdx.x >> 5);   // 138*8 = 1104
    int lane = threadIdx.x & 31;
    const float* src = ew + row * 70;
    float s = 0.f;
    for (int k = lane; k < 70; k += 32) { float v = src[k]; s += v * v; }
    #pragma unroll
    for (int o = 16; o > 0; o >>= 1) s += __shfl_xor_sync(0xffffffffu, s, o);
    float n = sqrtf(s);
    float sc = (n > 1.0f) ? 1.0f / (n + 1e-7f) : 1.0f;
    float* dst = g_wr + row * 70;
    for (int k = lane; k < 70; k += 32) dst[k] = src[k] * sc;
}

// ---------------- K1: e = x(65536x1104) @ wr(1104x70) ----------------
// BM=128, BN=72(pad), KT=16, 192 threads, DOUBLE-BUFFERED smem, 1 sync/iter
__global__ __launch_bounds__(192) void k_egemm(const float* __restrict__ x) {
    __shared__ float  sa[2][16][132];
    __shared__ float2 sb[2][16][72];
    const int tid = threadIdx.x;
    const int mb = blockIdx.x * 128;
    const int mg = tid / 12, ng = tid % 12;
    const int m0 = mg * 8, n0 = ng * 6;

    // precomputed staging indices
    int aM[3], aK[3]; bool aV[3];
    #pragma unroll
    for (int j = 0; j < 3; j++) {
        int i = tid + 192 * j;
        aV[j] = (i < 512); aM[j] = i >> 2; aK[j] = (i & 3) << 2;
    }
    int bK[6], bN[6];
    #pragma unroll
    for (int j = 0; j < 6; j++) {
        int i = tid + 192 * j;
        bK[j] = i / 72; bN[j] = i % 72;
    }

    float2 acc[4][6];
    #pragma unroll
    for (int p = 0; p < 4; p++)
        #pragma unroll
        for (int j = 0; j < 6; j++) acc[p][j] = make_float2(0.f, 0.f);

    float4 ra[3]; float rb[6];

    // prologue: load + store tile 0
    #pragma unroll
    for (int j = 0; j < 3; j++)
        if (aV[j]) ra[j] = *reinterpret_cast<const float4*>(x + (size_t)(mb + aM[j]) * 1104 + aK[j]);
    #pragma unroll
    for (int j = 0; j < 6; j++)
        rb[j] = (bN[j] < 70) ? g_wr[bK[j] * 70 + bN[j]] : 0.f;
    #pragma unroll
    for (int j = 0; j < 3; j++)
        if (aV[j]) {
            sa[0][aK[j] + 0][aM[j]] = ra[j].x; sa[0][aK[j] + 1][aM[j]] = ra[j].y;
            sa[0][aK[j] + 2][aM[j]] = ra[j].z; sa[0][aK[j] + 3][aM[j]] = ra[j].w;
        }
    #pragma unroll
    for (int j = 0; j < 6; j++) sb[0][bK[j]][bN[j]] = make_float2(rb[j], rb[j]);
    __syncthreads();

    for (int it = 0; it < 69; it++) {
        const int cur = it & 1;
        // issue next tile's global loads first (overlap with compute)
        if (it < 68) {
            const int kt = (it + 1) * 16;
            #pragma unroll
            for (int j = 0; j < 3; j++)
                if (aV[j]) ra[j] = *reinterpret_cast<const float4*>(x + (size_t)(mb + aM[j]) * 1104 + kt + aK[j]);
            #pragma unroll
            for (int j = 0; j < 6; j++)
                rb[j] = (bN[j] < 70) ? g_wr[(kt + bK[j]) * 70 + bN[j]] : 0.f;
        }
        // compute on current buffer
        #pragma unroll
        for (int kk = 0; kk < 16; kk++) {
            float4 a0 = *reinterpret_cast<const float4*>(&sa[cur][kk][m0]);
            float4 a1 = *reinterpret_cast<const float4*>(&sa[cur][kk][m0 + 4]);
            float2 ap[4] = { make_float2(a0.x, a0.y), make_float2(a0.z, a0.w),
                             make_float2(a1.x, a1.y), make_float2(a1.z, a1.w) };
            __align__(16) float2 bv[6];
            *reinterpret_cast<float4*>(&bv[0]) = *reinterpret_cast<const float4*>(&sb[cur][kk][n0]);
            *reinterpret_cast<float4*>(&bv[2]) = *reinterpret_cast<const float4*>(&sb[cur][kk][n0 + 2]);
            *reinterpret_cast<float4*>(&bv[4]) = *reinterpret_cast<const float4*>(&sb[cur][kk][n0 + 4]);
            #pragma unroll
            for (int p = 0; p < 4; p++)
                #pragma unroll
                for (int j = 0; j < 6; j++)
                    acc[p][j] = ffma2(ap[p], bv[j], acc[p][j]);
        }
        // stage next tile into the other buffer
        if (it < 68) {
            const int nxt = cur ^ 1;
            #pragma unroll
            for (int j = 0; j < 3; j++)
                if (aV[j]) {
                    sa[nxt][aK[j] + 0][aM[j]] = ra[j].x; sa[nxt][aK[j] + 1][aM[j]] = ra[j].y;
                    sa[nxt][aK[j] + 2][aM[j]] = ra[j].z; sa[nxt][aK[j] + 3][aM[j]] = ra[j].w;
                }
            #pragma unroll
            for (int j = 0; j < 6; j++) sb[nxt][bK[j]][bN[j]] = make_float2(rb[j], rb[j]);
        }
        __syncthreads();
    }

    #pragma unroll
    for (int p = 0; p < 4; p++) {
        int m = mb + m0 + 2 * p;
        #pragma unroll
        for (int j = 0; j < 6; j++) {
            int n = n0 + j;
            if (n < 70) {
                g_e[(size_t)m * 70 + n]       = acc[p][j].x;
                g_e[(size_t)(m + 1) * 70 + n] = acc[p][j].y;
            }
        }
    }
}

// ---------------- K2: xg plane gi = e(65536x70) @ w_ih[gi]^T + bias ----------------
__global__ __launch_bounds__(160) void k_xggemm(const float* __restrict__ wih,
                                                const float* __restrict__ bih,
                                                const float* __restrict__ bhh) {
    __shared__ float se[64 * 72];
    __shared__ float sw[70 * 74];
    const int tid = threadIdx.x;
    const int mb = blockIdx.x * 64;
    const int gi = blockIdx.y;
    const int mg = tid / 10, jg = tid % 10;
    const int m0 = mg * 4, u0 = jg * 7;

    for (int i = tid; i < 64 * 70; i += 160) {
        int m = i / 70, k = i % 70;
        se[m * 72 + k] = g_e[(size_t)(mb + m) * 70 + k];
    }
    for (int i = tid; i < 70 * 70; i += 160) {
        int u = i / 70, k = i % 70;
        sw[u * 74 + k] = wih[(gi * 70 + u) * 70 + k];
    }
    float2 acc[4][7];
    #pragma unroll
    for (int a = 0; a < 4; a++)
        #pragma unroll
        for (int c = 0; c < 7; c++) acc[a][c] = make_float2(0.f, 0.f);
    __syncthreads();

    #pragma unroll 5
    for (int kp = 0; kp < 35; kp++) {
        float2 av[4], wv[7];
        #pragma unroll
        for (int a = 0; a < 4; a++)
            av[a] = *reinterpret_cast<const float2*>(&se[(m0 + a) * 72 + 2 * kp]);
        #pragma unroll
        for (int c = 0; c < 7; c++)
            wv[c] = *reinterpret_cast<const float2*>(&sw[(u0 + c) * 74 + 2 * kp]);
        #pragma unroll
        for (int a = 0; a < 4; a++)
            #pragma unroll
            for (int c = 0; c < 7; c++)
                acc[a][c] = ffma2(av[a], wv[c], acc[a][c]);
    }
    float bs[7];
    #pragma unroll
    for (int c = 0; c < 7; c++) bs[c] = bih[gi * 70 + u0 + c] + bhh[gi * 70 + u0 + c];
    float* plane = g_xg + (size_t)gi * 65536 * 70;
    #pragma unroll
    for (int a = 0; a < 4; a++)
        #pragma unroll
        for (int c = 0; c < 7; c++)
            plane[(size_t)(mb + m0 + a) * 70 + u0 + c] = acc[a][c].x + acc[a][c].y + bs[c];
}

// ---------------- K3: LSTM recurrence ----------------
// 144 threads: tid = 2u + p. Thread computes TWO gate dots (p0: i,f; p1: g,o)
// with Whh rows register-resident. 2 shuffles + 1 barrier per step.
__global__ __launch_bounds__(144) void k_lstm(const float* __restrict__ whh) {
    __shared__ float s_h[2][72];
    const int b = blockIdx.x, tid = threadIdx.x;
    const int u = tid >> 1, p = tid & 1;
    const bool act = (u < 70);
    const int gA = p ? 2 : 0;   // p0: i ; p1: g
    const int gB = p ? 3 : 1;   // p0: f ; p1: o

    float2 wA[36], wB[36];
    #pragma unroll
    for (int i = 0; i < 36; i++) { wA[i] = make_float2(0.f, 0.f); wB[i] = make_float2(0.f, 0.f); }
    if (act) {
        const float* pa = whh + (gA * 70 + u) * 70;
        const float* pb = whh + (gB * 70 + u) * 70;
        #pragma unroll
        for (int i = 0; i < 35; i++) {
            wA[i] = *reinterpret_cast<const float2*>(pa + 2 * i);
            wB[i] = *reinterpret_cast<const float2*>(pb + 2 * i);
        }
    }
    reinterpret_cast<float*>(s_h)[tid] = 0.f;   // zero both 72-float buffers (144 threads)

    const float* xA = g_xg + ((size_t)gA * 65536 + (size_t)b * 512) * 70 + u;
    const float* xB = g_xg + ((size_t)gB * 65536 + (size_t)b * 512) * 70 + u;
    float xa = act ? xA[0] : 0.f;
    float xb = act ? xB[0] : 0.f;
    float* hs = g_hs + (size_t)b * 512 * 70 + u;
    float c = 0.f;
    __syncthreads();

    int buf = 0;
    for (int t = 0; t < 512; t++) {
        const float4* h4 = reinterpret_cast<const float4*>(s_h[buf]);
        float2 a0 = make_float2(0.f, 0.f), a1 = a0, b0 = a0, b1 = a0;
        #pragma unroll
        for (int q = 0; q < 18; q++) {
            float4 hq = h4[q];
            float2 hlo = make_float2(hq.x, hq.y);
            float2 hhi = make_float2(hq.z, hq.w);
            a0 = ffma2(wA[2 * q],     hlo, a0);
            a1 = ffma2(wA[2 * q + 1], hhi, a1);
            b0 = ffma2(wB[2 * q],     hlo, b0);
            b1 = ffma2(wB[2 * q + 1], hhi, b1);
        }
        float sA = xa + (a0.x + a0.y) + (a1.x + a1.y);
        float sB = xb + (b0.x + b0.y) + (b1.x + b1.y);

        if (act && t < 511) {                       // prefetch next step's xg
            xa = xA[(size_t)(t + 1) * 70];
            xb = xB[(size_t)(t + 1) * 70];
        }
        // p0: vA=sigmoid(i), vB=sigmoid(f);  p1: vA=tanh(g), vB=sigmoid(o)
        float xsA = p ? (sA + sA) : sA;
        float rA  = rcp_(1.0f + __expf(-xsA));
        float vA  = p ? (rA + rA - 1.0f) : rA;
        float vB  = rcp_(1.0f + __expf(-sB));

        float gg = __shfl_xor_sync(0xffffffffu, vA, 1);
        float go = __shfl_xor_sync(0xffffffffu, vB, 1);

        if (p == 0 && act) {
            c = vB * c + vA * gg;                   // f*c + i*g
            float r2 = rcp_(1.0f + __expf(-2.0f * c));
            float h = go * (r2 + r2 - 1.0f);        // o * tanh(c)
            s_h[buf ^ 1][u] = h;
            hs[(size_t)t * 70] = h;
        }
        __syncthreads();
        buf ^= 1;
    }
}

// ---------------- K4: attention energies, fused GEMM + relu + matvec ----------------
__global__ __launch_bounds__(256) void k_energy(const float* __restrict__ w1,
                                                const float* __restrict__ b1,
                                                const float* __restrict__ w2,
                                                const float* __restrict__ b2) {
    __shared__ float sh[64 * 72];
    __shared__ float sw1[64 * 74];
    const int tid = threadIdx.x;
    const int mb = blockIdx.x * 64;
    const int mg = tid >> 3, jg = tid & 7;

    for (int i = tid; i < 64 * 70; i += 256) {
        int m = i / 70, k = i % 70;
        sh[m * 72 + k] = g_hs[(size_t)(mb + m) * 70 + k];
    }
    for (int i = tid; i < 64 * 70; i += 256) {
        int j = i / 70, k = i % 70;
        sw1[j * 74 + k] = w1[i];
    }
    float2 acc0[8], acc1[8];
    #pragma unroll
    for (int cc = 0; cc < 8; cc++) { acc0[cc] = make_float2(0.f, 0.f); acc1[cc] = make_float2(0.f, 0.f); }
    __syncthreads();

    const int m0 = 2 * mg;
    #pragma unroll 5
    for (int kp = 0; kp < 35; kp++) {
        float2 h0 = *reinterpret_cast<const float2*>(&sh[m0 * 72 + 2 * kp]);
        float2 h1 = *reinterpret_cast<const float2*>(&sh[(m0 + 1) * 72 + 2 * kp]);
        #pragma unroll
        for (int cc = 0; cc < 8; cc++) {
            float2 wv = *reinterpret_cast<const float2*>(&sw1[(jg + 8 * cc) * 74 + 2 * kp]);
            acc0[cc] = ffma2(h0, wv, acc0[cc]);
            acc1[cc] = ffma2(h1, wv, acc1[cc]);
        }
    }
    float r0 = 0.f, r1 = 0.f;
    #pragma unroll
    for (int cc = 0; cc < 8; cc++) {
        int j = jg + 8 * cc;
        float bj = __ldg(&b1[j]), wj = __ldg(&w2[j]);
        float e0 = fmaxf(acc0[cc].x + acc0[cc].y + bj, 0.f);
        float e1 = fmaxf(acc1[cc].x + acc1[cc].y + bj, 0.f);
        r0 += e0 * wj; r1 += e1 * wj;
    }
    #pragma unroll
    for (int o = 4; o > 0; o >>= 1) {
        r0 += __shfl_down_sync(0xffffffffu, r0, o);
        r1 += __shfl_down_sync(0xffffffffu, r1, o);
    }
    if (jg == 0) {
        float bb = __ldg(&b2[0]);
        g_energy[mb + m0]     = r0 + bb;
        g_energy[mb + m0 + 1] = r1 + bb;
    }
}

// ---------------- K5: softmax over S, pooled, fc, final softmax ----------------
__global__ __launch_bounds__(280) void k_finish(const float* __restrict__ fcw,
                                                const float* __restrict__ fcb,
                                                float* __restrict__ out) {
    __shared__ float se[512];
    __shared__ float sr[512];
    __shared__ float s_pool[4][70];
    __shared__ float s_pl[70];
    __shared__ float s_lg[3];
    const int tid = threadIdx.x;
    const int b = blockIdx.x;

    for (int i = tid; i < 512; i += 280) { float v = g_energy[b * 512 + i]; se[i] = v; sr[i] = v; }
    __syncthreads();
    for (int st = 256; st > 0; st >>= 1) {
        for (int i = tid; i < st; i += 280) sr[i] = fmaxf(sr[i], sr[i + st]);
        __syncthreads();
    }
    float mx = sr[0];
    __syncthreads();
    for (int i = tid; i < 512; i += 280) { float ev = __expf(se[i] - mx); se[i] = ev; sr[i] = ev; }
    __syncthreads();
    for (int st = 256; st > 0; st >>= 1) {
        for (int i = tid; i < st; i += 280) sr[i] += sr[i + st];
        __syncthreads();
    }
    float inv = 1.0f / sr[0];

    const int h = tid % 70, ch = tid / 70;
    float p = 0.f;
    const float* base = g_hs + (size_t)b * 512 * 70;
    #pragma unroll 4
    for (int s = ch; s < 512; s += 4) p += base[(size_t)s * 70 + h] * se[s];
    s_pool[ch][h] = p;
    __syncthreads();
    if (ch == 0) s_pl[h] = (s_pool[0][h] + s_pool[1][h] + s_pool[2][h] + s_pool[3][h]) * inv;
    __syncthreads();
    if (tid < 3) {
        float lg = fcb[tid];
        for (int k = 0; k < 70; k++) lg += s_pl[k] * fcw[tid * 70 + k];
        s_lg[tid] = lg;
    }
    __syncthreads();
    if (tid < 3) {
        float m = fmaxf(s_lg[0], fmaxf(s_lg[1], s_lg[2]));
        float e0 = __expf(s_lg[0] - m), e1 = __expf(s_lg[1] - m), e2 = __expf(s_lg[2] - m);
        float ev = (tid == 0) ? e0 : ((tid == 1) ? e1 : e2);
        out[b * 3 + tid] = ev / (e0 + e1 + e2);
    }
}

// ---------------- launch ----------------
extern "C" void kernel_launch(void* const* d_in, const int* in_sizes, int n_in,
                              void* d_out, int out_size) {
    const float* x   = (const float*)d_in[0];
    const float* ew  = (const float*)d_in[1];
    const float* wih = (const float*)d_in[2];
    const float* whh = (const float*)d_in[3];
    const float* bih = (const float*)d_in[4];
    const float* bhh = (const float*)d_in[5];
    const float* aw1 = (const float*)d_in[6];
    const float* ab1 = (const float*)d_in[7];
    const float* aw2 = (const float*)d_in[8];
    const float* ab2 = (const float*)d_in[9];
    const float* fcw = (const float*)d_in[10];
    const float* fcb = (const float*)d_in[11];
    float* out = (float*)d_out;

    // renorm launched 3x (idempotent, ~2us each) so k_egemm lands in the
    // profiled launch slot that captured k_lstm in rounds 1-2.
    k_renorm<<<138, 256>>>(ew);
    k_renorm<<<138, 256>>>(ew);
    k_renorm<<<138, 256>>>(ew);
    k_egemm<<<512, 192>>>(x);
    k_xggemm<<<dim3(1024, 4), 160>>>(wih, bih, bhh);
    k_lstm<<<128, 144>>>(whh);
    k_energy<<<1024, 256>>>(aw1, ab1, aw2, ab2);
    k_finish<<<128, 280>>>(fcw, fcb, out);
}

// round 5
// speedup vs baseline: 2.4591x; 1.4533x over previous
#include <cuda_runtime.h>
#include <cuda_bf16.h>
#include <math.h>
#include <cstdint>

// ---------------- scratch (device globals: allocation-free) ----------------
static __device__ __nv_bfloat16 g_wbt_hi[80 * 1152];        // wr^T hi, [n][k], zero-padded
static __device__ __nv_bfloat16 g_wbt_lo[80 * 1152];        // wr^T lo
static __device__ float g_e[(size_t)65536 * 70];             // e = x @ wr
static __device__ float g_xg[(size_t)4 * 65536 * 70];        // xg, 4 gate planes [g][m][70]
static __device__ float g_hs[(size_t)65536 * 70];            // lstm hidden states
static __device__ float g_energy[65536];                     // attention energies

#define DEV_INLINE __device__ __forceinline__

DEV_INLINE float2 ffma2(float2 a, float2 b, float2 c) {
    unsigned long long ua = *reinterpret_cast<unsigned long long*>(&a);
    unsigned long long ub = *reinterpret_cast<unsigned long long*>(&b);
    unsigned long long uc = *reinterpret_cast<unsigned long long*>(&c);
    unsigned long long ud;
    asm("fma.rn.f32x2 %0, %1, %2, %3;" : "=l"(ud) : "l"(ua), "l"(ub), "l"(uc));
    return *reinterpret_cast<float2*>(&ud);
}
DEV_INLINE float rcp_(float x) { float r; asm("rcp.approx.f32 %0, %1;" : "=f"(r) : "f"(x)); return r; }

DEV_INLINE uint32_t smem_u32(const void* p) {
    uint32_t a;
    asm("{ .reg .u64 t; cvta.to.shared.u64 t, %1; cvt.u32.u64 %0, t; }" : "=r"(a) : "l"(p));
    return a;
}
DEV_INLINE uint32_t sw128(uint32_t off) { return off ^ ((off >> 3) & 0x70); }

DEV_INLINE void ldsm_x4(uint32_t a, uint32_t& r0, uint32_t& r1, uint32_t& r2, uint32_t& r3) {
    asm volatile("ldmatrix.sync.aligned.m8n8.x4.shared.b16 {%0,%1,%2,%3}, [%4];"
        : "=r"(r0), "=r"(r1), "=r"(r2), "=r"(r3) : "r"(a));
}
DEV_INLINE void ldsm_x2(uint32_t a, uint32_t& r0, uint32_t& r1) {
    asm volatile("ldmatrix.sync.aligned.m8n8.x2.shared.b16 {%0,%1}, [%2];"
        : "=r"(r0), "=r"(r1) : "r"(a));
}
DEV_INLINE void mma_bf16(float* c, uint32_t a0, uint32_t a1, uint32_t a2, uint32_t a3,
                         uint32_t b0, uint32_t b1) {
    asm volatile("mma.sync.aligned.m16n8k16.row.col.f32.bf16.bf16.f32 "
        "{%0,%1,%2,%3}, {%4,%5,%6,%7}, {%8,%9}, {%0,%1,%2,%3};"
        : "+f"(c[0]), "+f"(c[1]), "+f"(c[2]), "+f"(c[3])
        : "r"(a0), "r"(a1), "r"(a2), "r"(a3), "r"(b0), "r"(b1));
}

// ---------------- K0: renorm embed rows + bf16 hi/lo transpose ----------------
__global__ void k_renorm(const float* __restrict__ ew) {
    int row = blockIdx.x * 8 + (threadIdx.x >> 5);   // c index, 138*8 = 1104
    int lane = threadIdx.x & 31;
    const float* src = ew + row * 70;
    float s = 0.f;
    for (int k = lane; k < 70; k += 32) { float v = src[k]; s += v * v; }
    #pragma unroll
    for (int o = 16; o > 0; o >>= 1) s += __shfl_xor_sync(0xffffffffu, s, o);
    float n = sqrtf(s);
    float sc = (n > 1.0f) ? 1.0f / (n + 1e-7f) : 1.0f;
    for (int k = lane; k < 70; k += 32) {
        float v = src[k] * sc;
        __nv_bfloat16 h = __float2bfloat16_rn(v);
        float hf = __bfloat162float(h);
        __nv_bfloat16 l = __float2bfloat16_rn(v - hf);
        g_wbt_hi[k * 1152 + row] = h;     // transposed [n=k][k=row]
        g_wbt_lo[k * 1152 + row] = l;
    }
}

// ---------------- K1: e = x @ wr via mma.sync bf16 3-pass split ----------------
// CTA 128x72, BK=64 (SW128 rows), 256 threads / 8 warps, warp = 16 rows x 72 cols.
// smem: A hi/lo [2][128][64]bf16, B hi/lo [2][72][64]bf16 (double buffered).
static constexpr int EG_AH = 0;        // 2 x 16384
static constexpr int EG_AL = 32768;    // 2 x 16384
static constexpr int EG_BH = 65536;    // 2 x 9216
static constexpr int EG_BL = 83968;    // 2 x 9216
static constexpr int EG_SMEM = 102400;

__global__ void __launch_bounds__(256, 1) k_egemm(const float* __restrict__ x) {
    extern __shared__ char smem[];
    const uint32_t sb = smem_u32(smem);
    const int tid = threadIdx.x, lane = tid & 31, w = tid >> 5;
    const int mb = blockIdx.x * 128;
    const int m0 = w * 16;

    float acc[9][4];
    #pragma unroll
    for (int nt = 0; nt < 9; nt++)
        #pragma unroll
        for (int i = 0; i < 4; i++) acc[nt][i] = 0.f;

    float4 ra[8]; uint4 rbh[3], rbl[3];

    auto stage_loads = [&](int kt) {
        const int ktk = kt * 64;
        #pragma unroll
        for (int j = 0; j < 8; j++) {
            int i = tid + 256 * j;
            int row = i >> 4, q = i & 15;
            int kg = ktk + q * 4;
            ra[j] = (kg < 1104)
                ? *reinterpret_cast<const float4*>(x + (size_t)(mb + row) * 1104 + kg)
                : make_float4(0.f, 0.f, 0.f, 0.f);
        }
        #pragma unroll
        for (int j = 0; j < 3; j++) {
            int i = tid + 256 * j;
            if (i < 576) {
                int n = i >> 3, q = i & 7;
                size_t src = (size_t)n * 2304 + (size_t)ktk * 2 + q * 16;
                rbh[j] = *reinterpret_cast<const uint4*>(reinterpret_cast<const char*>(g_wbt_hi) + src);
                rbl[j] = *reinterpret_cast<const uint4*>(reinterpret_cast<const char*>(g_wbt_lo) + src);
            }
        }
    };
    auto stage_sts = [&](int buf) {
        char* ah = smem + EG_AH + buf * 16384;
        char* al = smem + EG_AL + buf * 16384;
        char* bh = smem + EG_BH + buf * 9216;
        char* bl = smem + EG_BL + buf * 9216;
        #pragma unroll
        for (int j = 0; j < 8; j++) {
            int i = tid + 256 * j;
            int row = i >> 4, q = i & 15;
            float4 v = ra[j];
            uint32_t ph01, ph23, pl01, pl23;
            asm("cvt.rn.bf16x2.f32 %0, %1, %2;" : "=r"(ph01) : "f"(v.y), "f"(v.x));
            asm("cvt.rn.bf16x2.f32 %0, %1, %2;" : "=r"(ph23) : "f"(v.w), "f"(v.z));
            float h0 = __uint_as_float(ph01 << 16), h1 = __uint_as_float(ph01 & 0xffff0000u);
            float h2 = __uint_as_float(ph23 << 16), h3 = __uint_as_float(ph23 & 0xffff0000u);
            asm("cvt.rn.bf16x2.f32 %0, %1, %2;" : "=r"(pl01) : "f"(v.y - h1), "f"(v.x - h0));
            asm("cvt.rn.bf16x2.f32 %0, %1, %2;" : "=r"(pl23) : "f"(v.w - h3), "f"(v.z - h2));
            uint32_t s = sw128(row * 128 + q * 8);
            *reinterpret_cast<uint2*>(ah + s) = make_uint2(ph01, ph23);
            *reinterpret_cast<uint2*>(al + s) = make_uint2(pl01, pl23);
        }
        #pragma unroll
        for (int j = 0; j < 3; j++) {
            int i = tid + 256 * j;
            if (i < 576) {
                int n = i >> 3, q = i & 7;
                uint32_t s = sw128(n * 128 + q * 16);
                *reinterpret_cast<uint4*>(bh + s) = rbh[j];
                *reinterpret_cast<uint4*>(bl + s) = rbl[j];
            }
        }
    };
    auto compute = [&](int buf) {
        const uint32_t u_ah = sb + EG_AH + buf * 16384;
        const uint32_t u_al = sb + EG_AL + buf * 16384;
        const uint32_t u_bh = sb + EG_BH + buf * 9216;
        const uint32_t u_bl = sb + EG_BL + buf * 9216;
        // ldmatrix lane->address patterns
        const uint32_t offA = (uint32_t)(m0 + (lane & 15)) * 128 + (lane >> 4) * 16;
        const uint32_t offB = (uint32_t)((lane & 7) + ((lane >> 4) << 3)) * 128 + ((lane >> 3) & 1) * 16;
        const uint32_t offB2 = (uint32_t)(64 + (lane & 7)) * 128 + ((lane >> 3) & 1) * 16;
        #pragma unroll
        for (int ks = 0; ks < 4; ks++) {
            const uint32_t kb = ks * 32;
            uint32_t ah0, ah1, ah2, ah3, al0, al1, al2, al3;
            ldsm_x4(u_ah + sw128(offA + kb), ah0, ah1, ah2, ah3);
            ldsm_x4(u_al + sw128(offA + kb), al0, al1, al2, al3);
            uint32_t bhf[18], blf[18];
            #pragma unroll
            for (int t = 0; t < 4; t++) {
                ldsm_x4(u_bh + sw128(offB + t * 2048 + kb),
                        bhf[4 * t], bhf[4 * t + 1], bhf[4 * t + 2], bhf[4 * t + 3]);
                ldsm_x4(u_bl + sw128(offB + t * 2048 + kb),
                        blf[4 * t], blf[4 * t + 1], blf[4 * t + 2], blf[4 * t + 3]);
            }
            ldsm_x2(u_bh + sw128(offB2 + kb), bhf[16], bhf[17]);
            ldsm_x2(u_bl + sw128(offB2 + kb), blf[16], blf[17]);
            #pragma unroll
            for (int nt = 0; nt < 9; nt++) {
                mma_bf16(acc[nt], ah0, ah1, ah2, ah3, bhf[2 * nt], bhf[2 * nt + 1]);  // hh
                mma_bf16(acc[nt], ah0, ah1, ah2, ah3, blf[2 * nt], blf[2 * nt + 1]);  // hl
                mma_bf16(acc[nt], al0, al1, al2, al3, bhf[2 * nt], bhf[2 * nt + 1]);  // lh
            }
        }
    };

    stage_loads(0);
    stage_sts(0);
    __syncthreads();
    for (int kt = 0; kt < 18; kt++) {
        const int buf = kt & 1;
        if (kt < 17) stage_loads(kt + 1);
        compute(buf);
        if (kt < 17) stage_sts(buf ^ 1);
        __syncthreads();
    }

    const int r0 = mb + m0 + (lane >> 2);
    const int cb = 2 * (lane & 3);
    #pragma unroll
    for (int nt = 0; nt < 9; nt++) {
        int col = nt * 8 + cb;
        if (col < 70) {
            *reinterpret_cast<float2*>(g_e + (size_t)r0 * 70 + col) = make_float2(acc[nt][0], acc[nt][1]);
            *reinterpret_cast<float2*>(g_e + (size_t)(r0 + 8) * 70 + col) = make_float2(acc[nt][2], acc[nt][3]);
        }
    }
}

// ---------------- K2: xg plane gi = e(65536x70) @ w_ih[gi]^T + bias ----------------
__global__ __launch_bounds__(160) void k_xggemm(const float* __restrict__ wih,
                                                const float* __restrict__ bih,
                                                const float* __restrict__ bhh) {
    __shared__ float se[64 * 72];
    __shared__ float sw[70 * 74];
    const int tid = threadIdx.x;
    const int mb = blockIdx.x * 64;
    const int gi = blockIdx.y;
    const int mg = tid / 10, jg = tid % 10;
    const int m0 = mg * 4, u0 = jg * 7;

    for (int i = tid; i < 64 * 70; i += 160) {
        int m = i / 70, k = i % 70;
        se[m * 72 + k] = g_e[(size_t)(mb + m) * 70 + k];
    }
    for (int i = tid; i < 70 * 70; i += 160) {
        int u = i / 70, k = i % 70;
        sw[u * 74 + k] = wih[(gi * 70 + u) * 70 + k];
    }
    float2 acc[4][7];
    #pragma unroll
    for (int a = 0; a < 4; a++)
        #pragma unroll
        for (int c = 0; c < 7; c++) acc[a][c] = make_float2(0.f, 0.f);
    __syncthreads();

    #pragma unroll 5
    for (int kp = 0; kp < 35; kp++) {
        float2 av[4], wv[7];
        #pragma unroll
        for (int a = 0; a < 4; a++)
            av[a] = *reinterpret_cast<const float2*>(&se[(m0 + a) * 72 + 2 * kp]);
        #pragma unroll
        for (int c = 0; c < 7; c++)
            wv[c] = *reinterpret_cast<const float2*>(&sw[(u0 + c) * 74 + 2 * kp]);
        #pragma unroll
        for (int a = 0; a < 4; a++)
            #pragma unroll
            for (int c = 0; c < 7; c++)
                acc[a][c] = ffma2(av[a], wv[c], acc[a][c]);
    }
    float bs[7];
    #pragma unroll
    for (int c = 0; c < 7; c++) bs[c] = bih[gi * 70 + u0 + c] + bhh[gi * 70 + u0 + c];
    float* plane = g_xg + (size_t)gi * 65536 * 70;
    #pragma unroll
    for (int a = 0; a < 4; a++)
        #pragma unroll
        for (int c = 0; c < 7; c++)
            plane[(size_t)(mb + m0 + a) * 70 + u0 + c] = acc[a][c].x + acc[a][c].y + bs[c];
}

// ---------------- K3: LSTM recurrence (144 threads, regs-resident Whh) ----------------
__global__ __launch_bounds__(144) void k_lstm(const float* __restrict__ whh) {
    __shared__ float s_h[2][72];
    const int b = blockIdx.x, tid = threadIdx.x;
    const int u = tid >> 1, p = tid & 1;
    const bool act = (u < 70);
    const int gA = p ? 2 : 0;
    const int gB = p ? 3 : 1;

    float2 wA[36], wB[36];
    #pragma unroll
    for (int i = 0; i < 36; i++) { wA[i] = make_float2(0.f, 0.f); wB[i] = make_float2(0.f, 0.f); }
    if (act) {
        const float* pa = whh + (gA * 70 + u) * 70;
        const float* pb = whh + (gB * 70 + u) * 70;
        #pragma unroll
        for (int i = 0; i < 35; i++) {
            wA[i] = *reinterpret_cast<const float2*>(pa + 2 * i);
            wB[i] = *reinterpret_cast<const float2*>(pb + 2 * i);
        }
    }
    reinterpret_cast<float*>(s_h)[tid] = 0.f;

    const float* xA = g_xg + ((size_t)gA * 65536 + (size_t)b * 512) * 70 + u;
    const float* xB = g_xg + ((size_t)gB * 65536 + (size_t)b * 512) * 70 + u;
    float xa = act ? xA[0] : 0.f;
    float xb = act ? xB[0] : 0.f;
    float* hs = g_hs + (size_t)b * 512 * 70 + u;
    float c = 0.f;
    __syncthreads();

    int buf = 0;
    for (int t = 0; t < 512; t++) {
        const float4* h4 = reinterpret_cast<const float4*>(s_h[buf]);
        float2 a0 = make_float2(0.f, 0.f), a1 = a0, b0 = a0, b1 = a0;
        #pragma unroll
        for (int q = 0; q < 18; q++) {
            float4 hq = h4[q];
            float2 hlo = make_float2(hq.x, hq.y);
            float2 hhi = make_float2(hq.z, hq.w);
            a0 = ffma2(wA[2 * q],     hlo, a0);
            a1 = ffma2(wA[2 * q + 1], hhi, a1);
            b0 = ffma2(wB[2 * q],     hlo, b0);
            b1 = ffma2(wB[2 * q + 1], hhi, b1);
        }
        float sA = xa + (a0.x + a0.y) + (a1.x + a1.y);
        float sB = xb + (b0.x + b0.y) + (b1.x + b1.y);

        if (act && t < 511) {
            xa = xA[(size_t)(t + 1) * 70];
            xb = xB[(size_t)(t + 1) * 70];
        }
        float xsA = p ? (sA + sA) : sA;
        float rA  = rcp_(1.0f + __expf(-xsA));
        float vA  = p ? (rA + rA - 1.0f) : rA;
        float vB  = rcp_(1.0f + __expf(-sB));

        float gg = __shfl_xor_sync(0xffffffffu, vA, 1);
        float go = __shfl_xor_sync(0xffffffffu, vB, 1);

        if (p == 0 && act) {
            c = vB * c + vA * gg;
            float r2 = rcp_(1.0f + __expf(-2.0f * c));
            float h = go * (r2 + r2 - 1.0f);
            s_h[buf ^ 1][u] = h;
            hs[(size_t)t * 70] = h;
        }
        __syncthreads();
        buf ^= 1;
    }
}

// ---------------- K4: attention energies ----------------
__global__ __launch_bounds__(256) void k_energy(const float* __restrict__ w1,
                                                const float* __restrict__ b1,
                                                const float* __restrict__ w2,
                                                const float* __restrict__ b2) {
    __shared__ float sh[64 * 72];
    __shared__ float sw1[64 * 74];
    const int tid = threadIdx.x;
    const int mb = blockIdx.x * 64;
    const int mg = tid >> 3, jg = tid & 7;

    for (int i = tid; i < 64 * 70; i += 256) {
        int m = i / 70, k = i % 70;
        sh[m * 72 + k] = g_hs[(size_t)(mb + m) * 70 + k];
    }
    for (int i = tid; i < 64 * 70; i += 256) {
        int j = i / 70, k = i % 70;
        sw1[j * 74 + k] = w1[i];
    }
    float2 acc0[8], acc1[8];
    #pragma unroll
    for (int cc = 0; cc < 8; cc++) { acc0[cc] = make_float2(0.f, 0.f); acc1[cc] = make_float2(0.f, 0.f); }
    __syncthreads();

    const int m0 = 2 * mg;
    #pragma unroll 5
    for (int kp = 0; kp < 35; kp++) {
        float2 h0 = *reinterpret_cast<const float2*>(&sh[m0 * 72 + 2 * kp]);
        float2 h1 = *reinterpret_cast<const float2*>(&sh[(m0 + 1) * 72 + 2 * kp]);
        #pragma unroll
        for (int cc = 0; cc < 8; cc++) {
            float2 wv = *reinterpret_cast<const float2*>(&sw1[(jg + 8 * cc) * 74 + 2 * kp]);
            acc0[cc] = ffma2(h0, wv, acc0[cc]);
            acc1[cc] = ffma2(h1, wv, acc1[cc]);
        }
    }
    float r0 = 0.f, r1 = 0.f;
    #pragma unroll
    for (int cc = 0; cc < 8; cc++) {
        int j = jg + 8 * cc;
        float bj = __ldg(&b1[j]), wj = __ldg(&w2[j]);
        float e0 = fmaxf(acc0[cc].x + acc0[cc].y + bj, 0.f);
        float e1 = fmaxf(acc1[cc].x + acc1[cc].y + bj, 0.f);
        r0 += e0 * wj; r1 += e1 * wj;
    }
    #pragma unroll
    for (int o = 4; o > 0; o >>= 1) {
        r0 += __shfl_down_sync(0xffffffffu, r0, o);
        r1 += __shfl_down_sync(0xffffffffu, r1, o);
    }
    if (jg == 0) {
        float bb = __ldg(&b2[0]);
        g_energy[mb + m0]     = r0 + bb;
        g_energy[mb + m0 + 1] = r1 + bb;
    }
}

// ---------------- K5: softmax over S, pooled, fc, final softmax ----------------
__global__ __launch_bounds__(280) void k_finish(const float* __restrict__ fcw,
                                                const float* __restrict__ fcb,
                                                float* __restrict__ out) {
    __shared__ float se[512];
    __shared__ float sr[512];
    __shared__ float s_pool[4][70];
    __shared__ float s_pl[70];
    __shared__ float s_lg[3];
    const int tid = threadIdx.x;
    const int b = blockIdx.x;

    for (int i = tid; i < 512; i += 280) { float v = g_energy[b * 512 + i]; se[i] = v; sr[i] = v; }
    __syncthreads();
    for (int st = 256; st > 0; st >>= 1) {
        for (int i = tid; i < st; i += 280) sr[i] = fmaxf(sr[i], sr[i + st]);
        __syncthreads();
    }
    float mx = sr[0];
    __syncthreads();
    for (int i = tid; i < 512; i += 280) { float ev = __expf(se[i] - mx); se[i] = ev; sr[i] = ev; }
    __syncthreads();
    for (int st = 256; st > 0; st >>= 1) {
        for (int i = tid; i < st; i += 280) sr[i] += sr[i + st];
        __syncthreads();
    }
    float inv = 1.0f / sr[0];

    const int h = tid % 70, ch = tid / 70;
    float p = 0.f;
    const float* base = g_hs + (size_t)b * 512 * 70;
    #pragma unroll 4
    for (int s = ch; s < 512; s += 4) p += base[(size_t)s * 70 + h] * se[s];
    s_pool[ch][h] = p;
    __syncthreads();
    if (ch == 0) s_pl[h] = (s_pool[0][h] + s_pool[1][h] + s_pool[2][h] + s_pool[3][h]) * inv;
    __syncthreads();
    if (tid < 3) {
        float lg = fcb[tid];
        for (int k = 0; k < 70; k++) lg += s_pl[k] * fcw[tid * 70 + k];
        s_lg[tid] = lg;
    }
    __syncthreads();
    if (tid < 3) {
        float m = fmaxf(s_lg[0], fmaxf(s_lg[1], s_lg[2]));
        float e0 = __expf(s_lg[0] - m), e1 = __expf(s_lg[1] - m), e2 = __expf(s_lg[2] - m);
        float ev = (tid == 0) ? e0 : ((tid == 1) ? e1 : e2);
        out[b * 3 + tid] = ev / (e0 + e1 + e2);
    }
}

// ---------------- launch ----------------
extern "C" void kernel_launch(void* const* d_in, const int* in_sizes, int n_in,
                              void* d_out, int out_size) {
    const float* x   = (const float*)d_in[0];
    const float* ew  = (const float*)d_in[1];
    const float* wih = (const float*)d_in[2];
    const float* whh = (const float*)d_in[3];
    const float* bih = (const float*)d_in[4];
    const float* bhh = (const float*)d_in[5];
    const float* aw1 = (const float*)d_in[6];
    const float* ab1 = (const float*)d_in[7];
    const float* aw2 = (const float*)d_in[8];
    const float* ab2 = (const float*)d_in[9];
    const float* fcw = (const float*)d_in[10];
    const float* fcb = (const float*)d_in[11];
    float* out = (float*)d_out;

    cudaFuncSetAttribute(k_egemm, cudaFuncAttributeMaxDynamicSharedMemorySize, EG_SMEM);

    // renorm x3: keeps k_egemm in the profiled launch slot (#4)
    k_renorm<<<138, 256>>>(ew);
    k_renorm<<<138, 256>>>(ew);
    k_renorm<<<138, 256>>>(ew);
    k_egemm<<<512, 256, EG_SMEM>>>(x);
    k_xggemm<<<dim3(1024, 4), 160>>>(wih, bih, bhh);
    k_lstm<<<128, 144>>>(whh);
    k_energy<<<1024, 256>>>(aw1, ab1, aw2, ab2);
    k_finish<<<128, 280>>>(fcw, fcb, out);
}